// round 13
// baseline (speedup 1.0000x reference)
#include <cuda_runtime.h>
#include <math.h>

#define T_   32
#define B_   32
#define H_   128
#define W_   128

// output layout offsets (floats)
#define OFF_LOGITS 4096
#define OFF_SR     135168
#define OFF_ACTIVE 135170
#define OFF_ROUTE  135171
#define OFF_CHAN   135427

// ---------------- persistent device state ----------------
__device__ float g_scores[T_ * B_ * 256];
__device__ __align__(16) float g_gate[T_ * B_ * 64];   // float2-loaded
__device__ int   g_y0[T_ * B_], g_x0[T_ * B_];
__device__ int   g_fcnt[T_ * B_ * 96];     // spike counts per (t,b,channel)
__device__ int   g_route[256];
__device__ int   g_chan[64];
__device__ int   g_active;
__device__ __align__(16) float g_rz[T_ * B_ * 64 * 128];  // resized periph frames (32 MB)
__device__ __align__(16) float g_head_wT[128 * 96];       // head_w transposed [o][c]
__device__ __align__(16) float g_route_wT[128 * 256];     // route_w transposed [o][k]

// packed fp32x2 FMA (Blackwell FFMA2) — bit-exact IEEE fp32 per lane
__device__ __forceinline__ float2 ffma2(float a, float2 w, float2 c) {
#if __CUDA_ARCH__ >= 1000
    union { float2 f; unsigned long long u; } A, W, C, R;
    A.f = make_float2(a, a); W.f = w; C.f = c;
    asm("fma.rn.f32x2 %0, %1, %2, %3;" : "=l"(R.u) : "l"(A.u), "l"(W.u), "l"(C.u));
    return R.f;
#else
    return make_float2(fmaf(a, w.x, c.x), fmaf(a, w.y, c.y));
#endif
}

// 6 taps of one conv row (3 x-positions x 2 input channels), channel-pair packed.
#define CONV_ROW(rp, wrow, acc) do {                       \
    float2 _i0 = ((const float2*)(rp))[0];                 \
    float2 _i1 = ((const float2*)(rp))[1];                 \
    float2 _i2 = ((const float2*)(rp))[2];                 \
    acc = ffma2(_i0.x, (wrow)[0][0], acc);                 \
    acc = ffma2(_i0.y, (wrow)[0][1], acc);                 \
    acc = ffma2(_i1.x, (wrow)[1][0], acc);                 \
    acc = ffma2(_i1.y, (wrow)[1][1], acc);                 \
    acc = ffma2(_i2.x, (wrow)[2][0], acc);                 \
    acc = ffma2(_i2.y, (wrow)[2][1], acc);                 \
} while (0)

__device__ __forceinline__ float evmask(float v) { return (fabsf(v) > 0.5f) ? v : 0.f; }

// ---------------- init (+ weight transpose for k_logits) ----------------
__global__ void k_init(const float* __restrict__ head_w, const float* __restrict__ route_w) {
    int i = blockIdx.x * blockDim.x + threadIdx.x;
    int stride = gridDim.x * blockDim.x;
    for (int j = i; j < T_ * B_ * 96; j += stride) g_fcnt[j] = 0;
    for (int j = i; j < 12288; j += stride) g_head_wT[(j & 127) * 96 + (j >> 7)] = head_w[j];
    for (int j = i; j < 32768; j += stride) g_route_wT[(j & 127) * 256 + (j >> 7)] = route_w[j];
    if (i < 256) g_route[i] = 0;
    if (i < 64)  g_chan[i]  = 0;
    if (i == 0)  g_active   = 0;
}

// ---------------- k_prep ----------------
// blocks [0,1024): per (t,b) scores/argmax/route/active + fovea conv -> sal -> KWTA gate
// blocks [1024, 1024+8192): periph resize precompute -> g_rz (8 output rows per block)
__global__ void __launch_bounds__(256, 4)
k_prep(const float* __restrict__ x_seq, const float* __restrict__ w_fovea) {
    __shared__ __align__(16) float sb[6984];
    int bx = blockIdx.x, tid = threadIdx.x;

    if (bx < 1024) {
        int b = bx & 31, t = bx >> 5;
        int tb = t * 32 + b;
        const float* x = x_seq + (size_t)tb * 32768;

        float* s_sc  = sb;                                   // 256
        unsigned long long* s_key = (unsigned long long*)(sb + 256);  // 256 ull
        int*   s_acnt = (int*)(sb + 768);                    // 256
        float* s_win  = sb + 1024;                           // 34*68 = 2312
        float* s_asum = sb + 3336;                           // 512
        float* s_sal  = sb + 3848;                           // 64
        float* s_thresh = sb + 3912;
        float* s_thr2   = sb + 3913;
        int*   s_y0p = (int*)(sb + 3914);
        int*   s_x0p = (int*)(sb + 3915);

        // ---- part 1: patch scores (same element order as scalar version) ----
        int py = tid >> 4, px = tid & 15;
        float sum = 0.f; int cnt = 0;
        for (int r = 0; r < 8; r++) {
            const float4* row = (const float4*)(x + ((py * 8 + r) * W_ + px * 8) * 2);
#pragma unroll
            for (int k4 = 0; k4 < 4; k4++) {
                float4 v4 = row[k4];
                float a;
                a = fabsf(v4.x); if (a > 0.5f) { cnt++; sum += a; }
                a = fabsf(v4.y); if (a > 0.5f) { cnt++; sum += a; }
                a = fabsf(v4.z); if (a > 0.5f) { cnt++; sum += a; }
                a = fabsf(v4.w); if (a > 0.5f) { cnt++; sum += a; }
            }
        }
        float sc = sum * (1.f / 128.f);
        s_sc[tid] = sc;
        g_scores[tb * 256 + tid] = sc;
        s_acnt[tid] = cnt;
        unsigned int fb = __float_as_uint(sc);   // sc >= 0 -> order-preserving
        s_key[tid] = (((unsigned long long)fb) << 32) | (unsigned long long)(0xFFFFFFFFu - (unsigned)tid);
        __syncthreads();

        // exact top-4 threshold (JAX top_k tie semantics)
        int cg = 0, ceq = 0;
        for (int j = 0; j < 256; j++) {
            float v = s_sc[j];
            cg  += (v > sc);
            ceq += (v == sc);
        }
        if (cg <= 3 && cg + ceq > 3) *s_thresh = sc;

        for (int off = 128; off > 0; off >>= 1) {
            __syncthreads();
            if (tid < off) {
                s_acnt[tid] += s_acnt[tid + off];
                if (s_key[tid + off] > s_key[tid]) s_key[tid] = s_key[tid + off];
            }
        }
        __syncthreads();

        if (sc >= *s_thresh) atomicAdd(&g_route[tid], 1);
        if (tid == 0) {
            atomicAdd(&g_active, s_acnt[0]);
            unsigned int low = (unsigned int)(s_key[0] & 0xFFFFFFFFull);
            int best = (int)(0xFFFFFFFFu - low);
            int cy = (best >> 4) * 8 + 4;
            int cx = (best & 15) * 8 + 4;
            int y0 = cy - 16; y0 = y0 < 0 ? 0 : (y0 > 96 ? 96 : y0);
            int x0 = cx - 16; x0 = x0 < 0 ? 0 : (x0 > 96 ? 96 : x0);
            *s_y0p = y0; *s_x0p = x0;
            g_y0[tb] = y0; g_x0[tb] = x0;
        }

        // ---- part 2: fovea window load (event-masked, zero-padded) ----
        for (int i = tid; i < 34 * 68; i += 256) s_win[i] = 0.f;
        __syncthreads();
        int y0 = *s_y0p, x0 = *s_x0p;       // x0,y0 even -> float4-aligned
        for (int i = tid; i < 512; i += 256) {
            int rr = i >> 4, c4 = i & 15;
            float4 xv = *(const float4*)&x[(size_t)(y0 + rr) * 256 + x0 * 2 + c4 * 4];
            float* dst = &s_win[(rr + 1) * 68 + c4 * 4 + 2];
            dst[0] = evmask(xv.x); dst[1] = evmask(xv.y);
            dst[2] = evmask(xv.z); dst[3] = evmask(xv.w);
        }
        __syncthreads();

        // ---- part 3: conv -> per-channel |ff| sums -> KWTA gate ----
        int p = tid & 31;           // channel pair
        int g = tid >> 5;           // row group (4 rows each)
        float2 w2[3][3][2];
#pragma unroll
        for (int di = 0; di < 3; di++)
#pragma unroll
            for (int dj = 0; dj < 3; dj++)
#pragma unroll
                for (int ci = 0; ci < 2; ci++)
                    w2[di][dj][ci] = *(const float2*)&w_fovea[((di * 3 + dj) * 2 + ci) * 64 + 2 * p];

        float2 asum = make_float2(0.f, 0.f);
        for (int rq = 0; rq < 4; rq++) {
            int row = g * 4 + rq;
#pragma unroll 4
            for (int j = 0; j < 32; j++) {
                float2 acc = make_float2(0.f, 0.f);
#pragma unroll
                for (int di = 0; di < 3; di++) {
                    const float* rp = &s_win[(row + di) * 68 + j * 2];
                    CONV_ROW(rp, w2[di], acc);
                }
                asum.x += fabsf(acc.x);
                asum.y += fabsf(acc.y);
            }
        }
        s_asum[g * 64 + 2 * p]     = asum.x;
        s_asum[g * 64 + 2 * p + 1] = asum.y;
        __syncthreads();
        if (tid < 64) {
            float s = 0.f;
#pragma unroll
            for (int gg = 0; gg < 8; gg++) s += s_asum[gg * 64 + tid];
            s_sal[tid] = s;
        }
        __syncthreads();
        if (tid < 64) {
            float vv = s_sal[tid];
            int cg2 = 0, ce2 = 0;
            for (int j = 0; j < 64; j++) {
                float u = s_sal[j];
                cg2 += (u > vv);
                ce2 += (u == vv);
            }
            if (cg2 <= 15 && cg2 + ce2 > 15) *s_thr2 = vv;
        }
        __syncthreads();
        if (tid < 64) {
            float gt = (s_sal[tid] >= *s_thr2) ? 1.f : 0.f;
            g_gate[tb * 64 + tid] = gt;
            if (gt > 0.f) atomicAdd(&g_chan[tid], 1);
        }
    } else {
        // ================= periph resize precompute: 8 output rows per block =================
        int rb = bx - 1024;
        int tb = rb >> 3;
        int oy0 = (rb & 7) * 8;
        int hr0 = 2 * oy0 - 1;              // global x-row of local h row 0 (18 rows)
        const float* x = x_seq + (size_t)tb * 32768;

        float* s_x = sb;                    // [18][260] zero-padded cols
        float* s_h = sb + 4680;             // [18][128]

        for (int i = tid; i < 4680; i += 256) s_x[i] = 0.f;
        __syncthreads();
        for (int i = tid; i < 18 * 64; i += 256) {      // 64 float4 per row
            int r = i >> 6, c4 = i & 63;
            int gr = hr0 + r;
            if (gr >= 0 && gr < 128) {
                float4 xv = *(const float4*)&x[(size_t)gr * 256 + c4 * 4];
                float* dst = &s_x[r * 260 + 2 + c4 * 4];
                dst[0] = evmask(xv.x); dst[1] = evmask(xv.y);
                dst[2] = evmask(xv.z); dst[3] = evmask(xv.w);
            }
        }
        __syncthreads();
        // horizontal resize (exact JAX antialias-linear weights; OOB taps weight 0)
        for (int i = tid; i < 2304; i += 256) {
            int r = i >> 7, rest = i & 127;
            int ox = rest >> 1, c = rest & 1;
            int kb; float w0, w1, wm, w3;
            if (ox == 0)       { kb = -1;  w0 = 0.f;       w1 = 3.f / 7.f; wm = 3.f / 7.f; w3 = 1.f / 7.f; }
            else if (ox == 63) { kb = 125; w0 = 1.f / 7.f; w1 = 3.f / 7.f; wm = 3.f / 7.f; w3 = 0.f; }
            else               { kb = 2 * ox - 1; w0 = 0.125f; w1 = 0.375f; wm = 0.375f; w3 = 0.125f; }
            const float* xr = &s_x[r * 260 + 2 + c];
            float vv = w0 * xr[kb * 2] + w1 * xr[(kb + 1) * 2]
                     + wm * xr[(kb + 2) * 2] + w3 * xr[(kb + 3) * 2];
            s_h[i] = vv;
        }
        __syncthreads();
        // vertical resize + store
        for (int i = tid; i < 1024; i += 256) {
            int lr = i >> 7, rest = i & 127;
            int oy = oy0 + lr;
            int jb; float w0, w1, wm, w3;
            if (oy == 0)       { jb = -1;  w0 = 0.f;       w1 = 3.f / 7.f; wm = 3.f / 7.f; w3 = 1.f / 7.f; }
            else if (oy == 63) { jb = 125; w0 = 1.f / 7.f; w1 = 3.f / 7.f; wm = 3.f / 7.f; w3 = 0.f; }
            else               { jb = 2 * oy - 1; w0 = 0.125f; w1 = 0.375f; wm = 0.375f; w3 = 0.125f; }
            int base = jb - hr0;
            float vv = w0 * s_h[base * 128 + rest]       + w1 * s_h[(base + 1) * 128 + rest]
                     + wm * s_h[(base + 2) * 128 + rest] + w3 * s_h[(base + 3) * 128 + rest];
            g_rz[(size_t)tb * 8192 + (size_t)oy * 128 + rest] = vv;
        }
    }
}

// ---------------- k_lif: R8 broadcast conv layout + 8-timestep staging ----------------
// blocks [0,512): fovea   — b = bx>>4, 2-row tile = bx&15
// blocks [512,1536): periph — b = (bx-512)>>5, 2-row tile = (bx-512)&31
__global__ void __launch_bounds__(256, 4)
k_lif(const float* __restrict__ x_seq,
      const float* __restrict__ w_fovea,
      const float* __restrict__ w_periph) {
    __shared__ __align__(16) float sbuf[5248];   // union: fovea 2176f+2048i, periph 4224f+1024i
    __shared__ int s_y[32], s_x[32];
    int bx = blockIdx.x;
    int tid = threadIdx.x;

    if (bx < 512) {
        // ================= fovea: 8-t staged windows, conv + gate + LIF ==========
        int b = bx >> 4, tile = bx & 15;
        float* s_in  = sbuf;                  // [8 t][4 rows][68] (t stride 272 = 1088B)
        int*   s_cnt = (int*)(sbuf + 2176);   // [32][64]

        for (int i = tid; i < 2176; i += 256) s_in[i] = 0.f;
        for (int i = tid; i < 2048; i += 256) s_cnt[i] = 0;
        if (tid < 32) { s_y[tid] = g_y0[tid * 32 + b]; s_x[tid] = g_x0[tid * 32 + b]; }

        int p  = tid & 31;         // channel pair (broadcast LDS within warp)
        int q  = (tid >> 5) & 1;   // row within tile
        int xq = tid >> 6;         // x quarter (0..3): 8 positions each

        float2 w2[3][3][2];
#pragma unroll
        for (int di = 0; di < 3; di++)
#pragma unroll
            for (int dj = 0; dj < 3; dj++)
#pragma unroll
                for (int ci = 0; ci < 2; ci++)
                    w2[di][dj][ci] = *(const float2*)&w_fovea[((di * 3 + dj) * 2 + ci) * 64 + 2 * p];

        float2 v[8];
#pragma unroll
        for (int j = 0; j < 8; j++) v[j] = make_float2(0.f, 0.f);

        int r0 = tile * 2;

        for (int ph = 0; ph < 4; ph++) {
            __syncthreads();   // prev phase conv done (also covers s_in zero + s_y on ph=0)
            // stage 8 timesteps of gaze windows (all 256 threads, 2 items each)
            for (int i = tid; i < 512; i += 256) {
                int tt = i >> 6, rr = (i >> 4) & 3, c4 = i & 15;
                int t = ph * 8 + tt;
                int lrow = r0 - 1 + rr;
                if (lrow >= 0 && lrow < 32) {
                    const float* x = x_seq + (size_t)(t * 32 + b) * 32768;
                    float4 xv = *(const float4*)&x[(size_t)(s_y[t] + lrow) * 256 + s_x[t] * 2 + c4 * 4];
                    float* dst = &s_in[tt * 272 + rr * 68 + c4 * 4 + 2];
                    dst[0] = evmask(xv.x); dst[1] = evmask(xv.y);
                    dst[2] = evmask(xv.z); dst[3] = evmask(xv.w);
                }
            }
            __syncthreads();

#pragma unroll
            for (int tt = 0; tt < 8; tt++) {
                int t = ph * 8 + tt;
                int tb = t * 32 + b;
                float2 g2 = *(const float2*)&g_gate[tb * 64 + 2 * p];
                const float* tbase = &s_in[tt * 272];
                int c0 = 0, c1 = 0;
#pragma unroll
                for (int j = 0; j < 8; j++) {
                    int xx = xq * 8 + j;
                    float2 acc = make_float2(0.f, 0.f);
#pragma unroll
                    for (int di = 0; di < 3; di++) {
                        const float* rp = &tbase[(q + di) * 68 + xx * 2];
                        CONV_ROW(rp, w2[di], acc);
                    }
                    float vx = 0.9f * v[j].x + acc.x * g2.x;
                    float vy = 0.9f * v[j].y + acc.y * g2.y;
                    if (vx > 1.0f) { vx -= 1.0f; c0++; }
                    if (vy > 1.0f) { vy -= 1.0f; c1++; }
                    v[j].x = vx; v[j].y = vy;
                }
                atomicAdd(&s_cnt[t * 64 + 2 * p],     c0);
                atomicAdd(&s_cnt[t * 64 + 2 * p + 1], c1);
            }
        }
        __syncthreads();
        for (int i = tid; i < 2048; i += 256) {
            int t = i >> 6, c = i & 63;
            int val = s_cnt[i];
            if (val) atomicAdd(&g_fcnt[(t * 32 + b) * 96 + c], val);
        }
    } else {
        // ================= periph: 8-t staged windows, conv + LIF ==========
        int pbx = bx - 512;
        int b = pbx >> 5, tile = pbx & 31;        // output rows [2*tile, 2*tile+2)
        float* s_rz  = sbuf;                       // [8 t][4 rows][132] (t stride 528 = 2112B)
        int*   s_cnt = (int*)(sbuf + 4224);        // [32][32]

        for (int i = tid; i < 4224; i += 256) s_rz[i] = 0.f;
        for (int i = tid; i < 1024; i += 256) s_cnt[i] = 0;

        int p  = tid & 15;   // channel pair
        int xg = tid >> 4;   // x group (0..15): 4 positions each

        float2 w2[3][3][2];
#pragma unroll
        for (int di = 0; di < 3; di++)
#pragma unroll
            for (int dj = 0; dj < 3; dj++)
#pragma unroll
                for (int ci = 0; ci < 2; ci++)
                    w2[di][dj][ci] = *(const float2*)&w_periph[((di * 3 + dj) * 2 + ci) * 32 + 2 * p];

        float2 v[2][4];
#pragma unroll
        for (int yo = 0; yo < 2; yo++)
#pragma unroll
            for (int j = 0; j < 4; j++) v[yo][j] = make_float2(0.f, 0.f);

        for (int ph = 0; ph < 4; ph++) {
            __syncthreads();   // prev phase conv done (also covers zero-init on ph=0)
            // stage 8 timesteps of window rows 2*tile-1..2*tile+2 (OOB rows stay zero)
            for (int i = tid; i < 1024; i += 256) {
                int tt = i >> 7, lr = (i >> 5) & 3, c4 = i & 31;
                int row = 2 * tile - 1 + lr;
                if (row >= 0 && row < 64) {
                    int t = ph * 8 + tt;
                    float4 rv = *(const float4*)&g_rz[(size_t)(t * 32 + b) * 8192 + (size_t)row * 128 + c4 * 4];
                    float* dst = &s_rz[tt * 528 + lr * 132 + c4 * 4 + 2];
                    dst[0] = rv.x; dst[1] = rv.y; dst[2] = rv.z; dst[3] = rv.w;
                }
            }
            __syncthreads();

#pragma unroll
            for (int tt = 0; tt < 8; tt++) {
                int t = ph * 8 + tt;
                const float* tbase = &s_rz[tt * 528];
                int c0 = 0, c1 = 0;
#pragma unroll
                for (int yo = 0; yo < 2; yo++) {
#pragma unroll
                    for (int j = 0; j < 4; j++) {
                        int xx = 4 * xg + j;
                        float2 acc = make_float2(0.f, 0.f);
#pragma unroll
                        for (int di = 0; di < 3; di++) {
                            const float* rp = &tbase[(yo + di) * 132 + xx * 2];
                            CONV_ROW(rp, w2[di], acc);
                        }
                        float vx = 0.9f * v[yo][j].x + acc.x;
                        float vy = 0.9f * v[yo][j].y + acc.y;
                        if (vx > 1.0f) { vx -= 1.0f; c0++; }
                        if (vy > 1.0f) { vy -= 1.0f; c1++; }
                        v[yo][j].x = vx; v[yo][j].y = vy;
                    }
                }
                atomicAdd(&s_cnt[t * 32 + 2 * p],     c0);
                atomicAdd(&s_cnt[t * 32 + 2 * p + 1], c1);
            }
        }
        __syncthreads();
        for (int i = tid; i < 1024; i += 256) {
            int t = i >> 5, c = i & 31;
            int val = s_cnt[i];
            if (val) atomicAdd(&g_fcnt[(t * 32 + b) * 96 + 64 + c], val);
        }
    }
}

// ---------------- k_logits: transposed weights, contiguous float4 reads ----------------
__global__ void __launch_bounds__(256, 6)
k_logits(const float* __restrict__ head_b, const float* __restrict__ route_b,
         float* __restrict__ out) {
    int g = blockIdx.x;      // tb = g*2 + ib
    int tid = threadIdx.x;
    int ib = tid >> 7, o = tid & 127;
    __shared__ float s_f[2][96];
    __shared__ float s_s[2][256];
    for (int i = tid; i < 2 * 96; i += 256) {
        int jb = i / 96, c = i % 96;
        float scale = (c < 64) ? (1.f / 1024.f) : (1.f / 4096.f);
        s_f[jb][c] = (float)g_fcnt[(g * 2 + jb) * 96 + c] * scale;
    }
    for (int i = tid; i < 2 * 256; i += 256) {
        int jb = i >> 8, k = i & 255;
        s_s[jb][k] = g_scores[(g * 2 + jb) * 256 + k];
    }
    __syncthreads();
    float acc = head_b[o] + route_b[o];
    const float4* hw = (const float4*)&g_head_wT[o * 96];
    for (int c4 = 0; c4 < 24; c4++) {
        float4 w = hw[c4];
        acc = fmaf(s_f[ib][c4 * 4 + 0], w.x, acc);
        acc = fmaf(s_f[ib][c4 * 4 + 1], w.y, acc);
        acc = fmaf(s_f[ib][c4 * 4 + 2], w.z, acc);
        acc = fmaf(s_f[ib][c4 * 4 + 3], w.w, acc);
    }
    const float4* rw = (const float4*)&g_route_wT[o * 256];
    for (int k4 = 0; k4 < 64; k4++) {
        float4 w = rw[k4];
        acc = fmaf(s_s[ib][k4 * 4 + 0], w.x, acc);
        acc = fmaf(s_s[ib][k4 * 4 + 1], w.y, acc);
        acc = fmaf(s_s[ib][k4 * 4 + 2], w.z, acc);
        acc = fmaf(s_s[ib][k4 * 4 + 3], w.w, acc);
    }
    out[OFF_LOGITS + (size_t)(g * 2 + ib) * 128 + o] = acc;
}

// ---------------- k_final: mean over T + stats ----------------
__global__ void k_final(float* __restrict__ out) {
    int bid = blockIdx.x, tid = threadIdx.x;
    if (bid < 32) {
        float acc = 0.f;
        for (int t = 0; t < 32; t++)
            acc += out[OFF_LOGITS + (size_t)(t * 32 + bid) * 128 + tid];
        out[bid * 128 + tid] = acc * (1.f / 32.f);
    } else {
        for (int k = tid; k < 256; k += 128)
            out[OFF_ROUTE + k] = (float)g_route[k] * (1.f / 1024.f);
        if (tid < 64)
            out[OFF_CHAN + tid] = (float)g_chan[tid] * (1.f / 1024.f);
        __shared__ int r0[128], r1[128];
        int c0 = 0, c1 = 0;
        for (int i = tid; i < T_ * B_ * 96; i += 128) {
            int c = i % 96;
            int vv = g_fcnt[i];
            if (c < 64) c0 += vv; else c1 += vv;
        }
        r0[tid] = c0; r1[tid] = c1;
        __syncthreads();
        for (int off = 64; off > 0; off >>= 1) {
            if (tid < off) { r0[tid] += r0[tid + off]; r1[tid] += r1[tid + off]; }
            __syncthreads();
        }
        if (tid == 0) {
            out[OFF_SR + 0] = (float)r0[0] * (1.f / 67108864.f);    // T*B*32*32*64
            out[OFF_SR + 1] = (float)r1[0] * (1.f / 134217728.f);   // T*B*64*64*32
            out[OFF_ACTIVE] = (float)g_active * (1.f / 33554432.f); // T*B*128*128*2
        }
    }
}

// ---------------- launch ----------------
extern "C" void kernel_launch(void* const* d_in, const int* in_sizes, int n_in,
                              void* d_out, int out_size) {
    const float* x_seq    = (const float*)d_in[0];
    const float* w_fovea  = (const float*)d_in[1];
    const float* w_periph = (const float*)d_in[2];
    const float* head_w   = (const float*)d_in[3];
    const float* head_b   = (const float*)d_in[4];
    const float* route_w  = (const float*)d_in[5];
    const float* route_b  = (const float*)d_in[6];
    float* out = (float*)d_out;

    k_init<<<384, 256>>>(head_w, route_w);
    k_prep<<<1024 + 8192, 256>>>(x_seq, w_fovea);
    k_lif<<<1536, 256>>>(x_seq, w_fovea, w_periph);
    k_logits<<<512, 256>>>(head_b, route_b, out);
    k_final<<<33, 128>>>(out);
}

// round 14
// speedup vs baseline: 1.0939x; 1.0939x over previous
#include <cuda_runtime.h>
#include <math.h>

#define T_   32
#define B_   32
#define H_   128
#define W_   128

// output layout offsets (floats)
#define OFF_LOGITS 4096
#define OFF_SR     135168
#define OFF_ACTIVE 135170
#define OFF_ROUTE  135171
#define OFF_CHAN   135427

// ---------------- persistent device state ----------------
__device__ float g_scores[T_ * B_ * 256];
__device__ __align__(16) float g_gate[T_ * B_ * 64];   // float2-loaded
__device__ int   g_y0[T_ * B_], g_x0[T_ * B_];
__device__ int   g_fcnt[T_ * B_ * 96];     // spike counts per (t,b,channel)
__device__ int   g_route[256];
__device__ int   g_chan[64];
__device__ int   g_active;
__device__ __align__(16) float g_rz[T_ * B_ * 64 * 128];  // resized periph frames (32 MB)

// packed fp32x2 FMA (Blackwell FFMA2) — bit-exact IEEE fp32 per lane
__device__ __forceinline__ float2 ffma2(float a, float2 w, float2 c) {
#if __CUDA_ARCH__ >= 1000
    union { float2 f; unsigned long long u; } A, W, C, R;
    A.f = make_float2(a, a); W.f = w; C.f = c;
    asm("fma.rn.f32x2 %0, %1, %2, %3;" : "=l"(R.u) : "l"(A.u), "l"(W.u), "l"(C.u));
    return R.f;
#else
    return make_float2(fmaf(a, w.x, c.x), fmaf(a, w.y, c.y));
#endif
}

// 6 taps of one conv row (3 x-positions x 2 input channels), channel-pair packed.
#define CONV_ROW(rp, wrow, acc) do {                       \
    float2 _i0 = ((const float2*)(rp))[0];                 \
    float2 _i1 = ((const float2*)(rp))[1];                 \
    float2 _i2 = ((const float2*)(rp))[2];                 \
    acc = ffma2(_i0.x, (wrow)[0][0], acc);                 \
    acc = ffma2(_i0.y, (wrow)[0][1], acc);                 \
    acc = ffma2(_i1.x, (wrow)[1][0], acc);                 \
    acc = ffma2(_i1.y, (wrow)[1][1], acc);                 \
    acc = ffma2(_i2.x, (wrow)[2][0], acc);                 \
    acc = ffma2(_i2.y, (wrow)[2][1], acc);                 \
} while (0)

__device__ __forceinline__ float evmask(float v) { return (fabsf(v) > 0.5f) ? v : 0.f; }

// ---------------- init ----------------
__global__ void k_init() {
    int i = blockIdx.x * blockDim.x + threadIdx.x;
    int stride = gridDim.x * blockDim.x;
    for (int j = i; j < T_ * B_ * 96; j += stride) g_fcnt[j] = 0;
    if (i < 256) g_route[i] = 0;
    if (i < 64)  g_chan[i]  = 0;
    if (i == 0)  g_active   = 0;
}

// ---------------- k_prep ----------------
// blocks [0,1024): per (t,b) scores/argmax/route/active + fovea conv -> sal -> KWTA gate
// blocks [1024, 1024+8192): periph resize precompute -> g_rz (8 output rows per block)
__global__ void __launch_bounds__(256, 4)
k_prep(const float* __restrict__ x_seq, const float* __restrict__ w_fovea) {
    __shared__ __align__(16) float sb[6984];
    int bx = blockIdx.x, tid = threadIdx.x;

    if (bx < 1024) {
        int b = bx & 31, t = bx >> 5;
        int tb = t * 32 + b;
        const float* x = x_seq + (size_t)tb * 32768;

        float* s_sc  = sb;                                   // 256
        unsigned long long* s_key = (unsigned long long*)(sb + 256);  // 256 ull
        int*   s_acnt = (int*)(sb + 768);                    // 256
        float* s_win  = sb + 1024;                           // 34*68 = 2312
        float* s_asum = sb + 3336;                           // 512
        float* s_sal  = sb + 3848;                           // 64
        float* s_thresh = sb + 3912;
        float* s_thr2   = sb + 3913;
        int*   s_y0p = (int*)(sb + 3914);
        int*   s_x0p = (int*)(sb + 3915);

        // ---- part 1: patch scores (same element order as scalar version) ----
        int py = tid >> 4, px = tid & 15;
        float sum = 0.f; int cnt = 0;
        for (int r = 0; r < 8; r++) {
            const float4* row = (const float4*)(x + ((py * 8 + r) * W_ + px * 8) * 2);
#pragma unroll
            for (int k4 = 0; k4 < 4; k4++) {
                float4 v4 = row[k4];
                float a;
                a = fabsf(v4.x); if (a > 0.5f) { cnt++; sum += a; }
                a = fabsf(v4.y); if (a > 0.5f) { cnt++; sum += a; }
                a = fabsf(v4.z); if (a > 0.5f) { cnt++; sum += a; }
                a = fabsf(v4.w); if (a > 0.5f) { cnt++; sum += a; }
            }
        }
        float sc = sum * (1.f / 128.f);
        s_sc[tid] = sc;
        g_scores[tb * 256 + tid] = sc;
        s_acnt[tid] = cnt;
        unsigned int fb = __float_as_uint(sc);   // sc >= 0 -> order-preserving
        s_key[tid] = (((unsigned long long)fb) << 32) | (unsigned long long)(0xFFFFFFFFu - (unsigned)tid);
        __syncthreads();

        // exact top-4 threshold (JAX top_k tie semantics)
        int cg = 0, ceq = 0;
        for (int j = 0; j < 256; j++) {
            float v = s_sc[j];
            cg  += (v > sc);
            ceq += (v == sc);
        }
        if (cg <= 3 && cg + ceq > 3) *s_thresh = sc;

        for (int off = 128; off > 0; off >>= 1) {
            __syncthreads();
            if (tid < off) {
                s_acnt[tid] += s_acnt[tid + off];
                if (s_key[tid + off] > s_key[tid]) s_key[tid] = s_key[tid + off];
            }
        }
        __syncthreads();

        if (sc >= *s_thresh) atomicAdd(&g_route[tid], 1);
        if (tid == 0) {
            atomicAdd(&g_active, s_acnt[0]);
            unsigned int low = (unsigned int)(s_key[0] & 0xFFFFFFFFull);
            int best = (int)(0xFFFFFFFFu - low);
            int cy = (best >> 4) * 8 + 4;
            int cx = (best & 15) * 8 + 4;
            int y0 = cy - 16; y0 = y0 < 0 ? 0 : (y0 > 96 ? 96 : y0);
            int x0 = cx - 16; x0 = x0 < 0 ? 0 : (x0 > 96 ? 96 : x0);
            *s_y0p = y0; *s_x0p = x0;
            g_y0[tb] = y0; g_x0[tb] = x0;
        }

        // ---- part 2: fovea window load (event-masked, zero-padded) ----
        for (int i = tid; i < 34 * 68; i += 256) s_win[i] = 0.f;
        __syncthreads();
        int y0 = *s_y0p, x0 = *s_x0p;       // x0,y0 even -> float4-aligned
        for (int i = tid; i < 512; i += 256) {
            int rr = i >> 4, c4 = i & 15;
            float4 xv = *(const float4*)&x[(size_t)(y0 + rr) * 256 + x0 * 2 + c4 * 4];
            float* dst = &s_win[(rr + 1) * 68 + c4 * 4 + 2];
            dst[0] = evmask(xv.x); dst[1] = evmask(xv.y);
            dst[2] = evmask(xv.z); dst[3] = evmask(xv.w);
        }
        __syncthreads();

        // ---- part 3: conv -> per-channel |ff| sums -> KWTA gate ----
        int p = tid & 31;           // channel pair
        int g = tid >> 5;           // row group (4 rows each)
        float2 w2[3][3][2];
#pragma unroll
        for (int di = 0; di < 3; di++)
#pragma unroll
            for (int dj = 0; dj < 3; dj++)
#pragma unroll
                for (int ci = 0; ci < 2; ci++)
                    w2[di][dj][ci] = *(const float2*)&w_fovea[((di * 3 + dj) * 2 + ci) * 64 + 2 * p];

        float2 asum = make_float2(0.f, 0.f);
        for (int rq = 0; rq < 4; rq++) {
            int row = g * 4 + rq;
#pragma unroll 4
            for (int j = 0; j < 32; j++) {
                float2 acc = make_float2(0.f, 0.f);
#pragma unroll
                for (int di = 0; di < 3; di++) {
                    const float* rp = &s_win[(row + di) * 68 + j * 2];
                    CONV_ROW(rp, w2[di], acc);
                }
                asum.x += fabsf(acc.x);
                asum.y += fabsf(acc.y);
            }
        }
        s_asum[g * 64 + 2 * p]     = asum.x;
        s_asum[g * 64 + 2 * p + 1] = asum.y;
        __syncthreads();
        if (tid < 64) {
            float s = 0.f;
#pragma unroll
            for (int gg = 0; gg < 8; gg++) s += s_asum[gg * 64 + tid];
            s_sal[tid] = s;
        }
        __syncthreads();
        if (tid < 64) {
            float vv = s_sal[tid];
            int cg2 = 0, ce2 = 0;
            for (int j = 0; j < 64; j++) {
                float u = s_sal[j];
                cg2 += (u > vv);
                ce2 += (u == vv);
            }
            if (cg2 <= 15 && cg2 + ce2 > 15) *s_thr2 = vv;
        }
        __syncthreads();
        if (tid < 64) {
            float gt = (s_sal[tid] >= *s_thr2) ? 1.f : 0.f;
            g_gate[tb * 64 + tid] = gt;
            if (gt > 0.f) atomicAdd(&g_chan[tid], 1);
        }
    } else {
        // ================= periph resize precompute: 8 output rows per block =================
        int rb = bx - 1024;
        int tb = rb >> 3;
        int oy0 = (rb & 7) * 8;
        int hr0 = 2 * oy0 - 1;              // global x-row of local h row 0 (18 rows)
        const float* x = x_seq + (size_t)tb * 32768;

        float* s_x = sb;                    // [18][260] zero-padded cols
        float* s_h = sb + 4680;             // [18][128]

        for (int i = tid; i < 4680; i += 256) s_x[i] = 0.f;
        __syncthreads();
        for (int i = tid; i < 18 * 64; i += 256) {      // 64 float4 per row
            int r = i >> 6, c4 = i & 63;
            int gr = hr0 + r;
            if (gr >= 0 && gr < 128) {
                float4 xv = *(const float4*)&x[(size_t)gr * 256 + c4 * 4];
                float* dst = &s_x[r * 260 + 2 + c4 * 4];
                dst[0] = evmask(xv.x); dst[1] = evmask(xv.y);
                dst[2] = evmask(xv.z); dst[3] = evmask(xv.w);
            }
        }
        __syncthreads();
        // horizontal resize (exact JAX antialias-linear weights; OOB taps weight 0)
        for (int i = tid; i < 2304; i += 256) {
            int r = i >> 7, rest = i & 127;
            int ox = rest >> 1, c = rest & 1;
            int kb; float w0, w1, wm, w3;
            if (ox == 0)       { kb = -1;  w0 = 0.f;       w1 = 3.f / 7.f; wm = 3.f / 7.f; w3 = 1.f / 7.f; }
            else if (ox == 63) { kb = 125; w0 = 1.f / 7.f; w1 = 3.f / 7.f; wm = 3.f / 7.f; w3 = 0.f; }
            else               { kb = 2 * ox - 1; w0 = 0.125f; w1 = 0.375f; wm = 0.375f; w3 = 0.125f; }
            const float* xr = &s_x[r * 260 + 2 + c];
            float vv = w0 * xr[kb * 2] + w1 * xr[(kb + 1) * 2]
                     + wm * xr[(kb + 2) * 2] + w3 * xr[(kb + 3) * 2];
            s_h[i] = vv;
        }
        __syncthreads();
        // vertical resize + store
        for (int i = tid; i < 1024; i += 256) {
            int lr = i >> 7, rest = i & 127;
            int oy = oy0 + lr;
            int jb; float w0, w1, wm, w3;
            if (oy == 0)       { jb = -1;  w0 = 0.f;       w1 = 3.f / 7.f; wm = 3.f / 7.f; w3 = 1.f / 7.f; }
            else if (oy == 63) { jb = 125; w0 = 1.f / 7.f; w1 = 3.f / 7.f; wm = 3.f / 7.f; w3 = 0.f; }
            else               { jb = 2 * oy - 1; w0 = 0.125f; w1 = 0.375f; wm = 0.375f; w3 = 0.125f; }
            int base = jb - hr0;
            float vv = w0 * s_h[base * 128 + rest]       + w1 * s_h[(base + 1) * 128 + rest]
                     + wm * s_h[(base + 2) * 128 + rest] + w3 * s_h[(base + 3) * 128 + rest];
            g_rz[(size_t)tb * 8192 + (size_t)oy * 128 + rest] = vv;
        }
    }
}

// ---------------- k_lif: R8 broadcast conv layout + 8-timestep staging ----------------
// blocks [0,512): fovea   — b = bx>>4, 2-row tile = bx&15
// blocks [512,1536): periph — b = (bx-512)>>5, 2-row tile = (bx-512)&31
__global__ void __launch_bounds__(256, 4)
k_lif(const float* __restrict__ x_seq,
      const float* __restrict__ w_fovea,
      const float* __restrict__ w_periph) {
    __shared__ __align__(16) float sbuf[5248];   // union: fovea 2176f+2048i, periph 4224f+1024i
    __shared__ int s_y[32], s_x[32];
    int bx = blockIdx.x;
    int tid = threadIdx.x;

    if (bx < 512) {
        // ================= fovea: 8-t staged windows, conv + gate + LIF ==========
        int b = bx >> 4, tile = bx & 15;
        float* s_in  = sbuf;                  // [8 t][4 rows][68] (t stride 272 = 1088B)
        int*   s_cnt = (int*)(sbuf + 2176);   // [32][64]

        for (int i = tid; i < 2176; i += 256) s_in[i] = 0.f;
        for (int i = tid; i < 2048; i += 256) s_cnt[i] = 0;
        if (tid < 32) { s_y[tid] = g_y0[tid * 32 + b]; s_x[tid] = g_x0[tid * 32 + b]; }

        int p  = tid & 31;         // channel pair (broadcast LDS within warp)
        int q  = (tid >> 5) & 1;   // row within tile
        int xq = tid >> 6;         // x quarter (0..3): 8 positions each

        float2 w2[3][3][2];
#pragma unroll
        for (int di = 0; di < 3; di++)
#pragma unroll
            for (int dj = 0; dj < 3; dj++)
#pragma unroll
                for (int ci = 0; ci < 2; ci++)
                    w2[di][dj][ci] = *(const float2*)&w_fovea[((di * 3 + dj) * 2 + ci) * 64 + 2 * p];

        float2 v[8];
#pragma unroll
        for (int j = 0; j < 8; j++) v[j] = make_float2(0.f, 0.f);

        int r0 = tile * 2;

        for (int ph = 0; ph < 4; ph++) {
            __syncthreads();   // prev phase conv done (also covers s_in zero + s_y on ph=0)
            // stage 8 timesteps of gaze windows (all 256 threads, 2 items each)
            for (int i = tid; i < 512; i += 256) {
                int tt = i >> 6, rr = (i >> 4) & 3, c4 = i & 15;
                int t = ph * 8 + tt;
                int lrow = r0 - 1 + rr;
                if (lrow >= 0 && lrow < 32) {
                    const float* x = x_seq + (size_t)(t * 32 + b) * 32768;
                    float4 xv = *(const float4*)&x[(size_t)(s_y[t] + lrow) * 256 + s_x[t] * 2 + c4 * 4];
                    float* dst = &s_in[tt * 272 + rr * 68 + c4 * 4 + 2];
                    dst[0] = evmask(xv.x); dst[1] = evmask(xv.y);
                    dst[2] = evmask(xv.z); dst[3] = evmask(xv.w);
                }
            }
            __syncthreads();

#pragma unroll
            for (int tt = 0; tt < 8; tt++) {
                int t = ph * 8 + tt;
                int tb = t * 32 + b;
                float2 g2 = *(const float2*)&g_gate[tb * 64 + 2 * p];
                const float* tbase = &s_in[tt * 272];
                int c0 = 0, c1 = 0;
#pragma unroll
                for (int j = 0; j < 8; j++) {
                    int xx = xq * 8 + j;
                    float2 acc = make_float2(0.f, 0.f);
#pragma unroll
                    for (int di = 0; di < 3; di++) {
                        const float* rp = &tbase[(q + di) * 68 + xx * 2];
                        CONV_ROW(rp, w2[di], acc);
                    }
                    float vx = 0.9f * v[j].x + acc.x * g2.x;
                    float vy = 0.9f * v[j].y + acc.y * g2.y;
                    if (vx > 1.0f) { vx -= 1.0f; c0++; }
                    if (vy > 1.0f) { vy -= 1.0f; c1++; }
                    v[j].x = vx; v[j].y = vy;
                }
                atomicAdd(&s_cnt[t * 64 + 2 * p],     c0);
                atomicAdd(&s_cnt[t * 64 + 2 * p + 1], c1);
            }
        }
        __syncthreads();
        for (int i = tid; i < 2048; i += 256) {
            int t = i >> 6, c = i & 63;
            int val = s_cnt[i];
            if (val) atomicAdd(&g_fcnt[(t * 32 + b) * 96 + c], val);
        }
    } else {
        // ================= periph: 8-t staged windows, conv + LIF ==========
        int pbx = bx - 512;
        int b = pbx >> 5, tile = pbx & 31;        // output rows [2*tile, 2*tile+2)
        float* s_rz  = sbuf;                       // [8 t][4 rows][132] (t stride 528 = 2112B)
        int*   s_cnt = (int*)(sbuf + 4224);        // [32][32]

        for (int i = tid; i < 4224; i += 256) s_rz[i] = 0.f;
        for (int i = tid; i < 1024; i += 256) s_cnt[i] = 0;

        int p  = tid & 15;   // channel pair
        int xg = tid >> 4;   // x group (0..15): 4 positions each

        float2 w2[3][3][2];
#pragma unroll
        for (int di = 0; di < 3; di++)
#pragma unroll
            for (int dj = 0; dj < 3; dj++)
#pragma unroll
                for (int ci = 0; ci < 2; ci++)
                    w2[di][dj][ci] = *(const float2*)&w_periph[((di * 3 + dj) * 2 + ci) * 32 + 2 * p];

        float2 v[2][4];
#pragma unroll
        for (int yo = 0; yo < 2; yo++)
#pragma unroll
            for (int j = 0; j < 4; j++) v[yo][j] = make_float2(0.f, 0.f);

        for (int ph = 0; ph < 4; ph++) {
            __syncthreads();   // prev phase conv done (also covers zero-init on ph=0)
            // stage 8 timesteps of window rows 2*tile-1..2*tile+2 (OOB rows stay zero)
            for (int i = tid; i < 1024; i += 256) {
                int tt = i >> 7, lr = (i >> 5) & 3, c4 = i & 31;
                int row = 2 * tile - 1 + lr;
                if (row >= 0 && row < 64) {
                    int t = ph * 8 + tt;
                    float4 rv = *(const float4*)&g_rz[(size_t)(t * 32 + b) * 8192 + (size_t)row * 128 + c4 * 4];
                    float* dst = &s_rz[tt * 528 + lr * 132 + c4 * 4 + 2];
                    dst[0] = rv.x; dst[1] = rv.y; dst[2] = rv.z; dst[3] = rv.w;
                }
            }
            __syncthreads();

#pragma unroll
            for (int tt = 0; tt < 8; tt++) {
                int t = ph * 8 + tt;
                const float* tbase = &s_rz[tt * 528];
                int c0 = 0, c1 = 0;
#pragma unroll
                for (int yo = 0; yo < 2; yo++) {
#pragma unroll
                    for (int j = 0; j < 4; j++) {
                        int xx = 4 * xg + j;
                        float2 acc = make_float2(0.f, 0.f);
#pragma unroll
                        for (int di = 0; di < 3; di++) {
                            const float* rp = &tbase[(yo + di) * 132 + xx * 2];
                            CONV_ROW(rp, w2[di], acc);
                        }
                        float vx = 0.9f * v[yo][j].x + acc.x;
                        float vy = 0.9f * v[yo][j].y + acc.y;
                        if (vx > 1.0f) { vx -= 1.0f; c0++; }
                        if (vy > 1.0f) { vy -= 1.0f; c1++; }
                        v[yo][j].x = vx; v[yo][j].y = vy;
                    }
                }
                atomicAdd(&s_cnt[t * 32 + 2 * p],     c0);
                atomicAdd(&s_cnt[t * 32 + 2 * p + 1], c1);
            }
        }
        __syncthreads();
        for (int i = tid; i < 1024; i += 256) {
            int t = i >> 5, c = i & 31;
            int val = s_cnt[i];
            if (val) atomicAdd(&g_fcnt[(t * 32 + b) * 96 + 64 + c], val);
        }
    }
}

// ---------------- k_logits: 2 tb per block, 512 blocks, coalesced weights (R12 version) ----
__global__ void __launch_bounds__(256, 6)
k_logits(const float* __restrict__ head_w, const float* __restrict__ head_b,
         const float* __restrict__ route_w, const float* __restrict__ route_b,
         float* __restrict__ out) {
    int g = blockIdx.x;      // tb = g*2 + ib
    int tid = threadIdx.x;
    int ib = tid >> 7, o = tid & 127;
    __shared__ float s_f[2][96];
    __shared__ float s_s[2][256];
    for (int i = tid; i < 2 * 96; i += 256) {
        int jb = i / 96, c = i % 96;
        float scale = (c < 64) ? (1.f / 1024.f) : (1.f / 4096.f);
        s_f[jb][c] = (float)g_fcnt[(g * 2 + jb) * 96 + c] * scale;
    }
    for (int i = tid; i < 2 * 256; i += 256) {
        int jb = i >> 8, k = i & 255;
        s_s[jb][k] = g_scores[(g * 2 + jb) * 256 + k];
    }
    __syncthreads();
    float acc = head_b[o] + route_b[o];
    for (int c = 0; c < 96; c++)  acc = fmaf(s_f[ib][c], head_w[c * 128 + o], acc);
    for (int k = 0; k < 256; k++) acc = fmaf(s_s[ib][k], route_w[k * 128 + o], acc);
    out[OFF_LOGITS + (size_t)(g * 2 + ib) * 128 + o] = acc;
}

// ---------------- k_final: mean over T + stats ----------------
__global__ void k_final(float* __restrict__ out) {
    int bid = blockIdx.x, tid = threadIdx.x;
    if (bid < 32) {
        float acc = 0.f;
        for (int t = 0; t < 32; t++)
            acc += out[OFF_LOGITS + (size_t)(t * 32 + bid) * 128 + tid];
        out[bid * 128 + tid] = acc * (1.f / 32.f);
    } else {
        for (int k = tid; k < 256; k += 128)
            out[OFF_ROUTE + k] = (float)g_route[k] * (1.f / 1024.f);
        if (tid < 64)
            out[OFF_CHAN + tid] = (float)g_chan[tid] * (1.f / 1024.f);
        __shared__ int r0[128], r1[128];
        int c0 = 0, c1 = 0;
        for (int i = tid; i < T_ * B_ * 96; i += 128) {
            int c = i % 96;
            int vv = g_fcnt[i];
            if (c < 64) c0 += vv; else c1 += vv;
        }
        r0[tid] = c0; r1[tid] = c1;
        __syncthreads();
        for (int off = 64; off > 0; off >>= 1) {
            if (tid < off) { r0[tid] += r0[tid + off]; r1[tid] += r1[tid + off]; }
            __syncthreads();
        }
        if (tid == 0) {
            out[OFF_SR + 0] = (float)r0[0] * (1.f / 67108864.f);    // T*B*32*32*64
            out[OFF_SR + 1] = (float)r1[0] * (1.f / 134217728.f);   // T*B*64*64*32
            out[OFF_ACTIVE] = (float)g_active * (1.f / 33554432.f); // T*B*128*128*2
        }
    }
}

// ---------------- launch ----------------
extern "C" void kernel_launch(void* const* d_in, const int* in_sizes, int n_in,
                              void* d_out, int out_size) {
    const float* x_seq    = (const float*)d_in[0];
    const float* w_fovea  = (const float*)d_in[1];
    const float* w_periph = (const float*)d_in[2];
    const float* head_w   = (const float*)d_in[3];
    const float* head_b   = (const float*)d_in[4];
    const float* route_w  = (const float*)d_in[5];
    const float* route_b  = (const float*)d_in[6];
    float* out = (float*)d_out;

    k_init<<<384, 256>>>();
    k_prep<<<1024 + 8192, 256>>>(x_seq, w_fovea);
    k_lif<<<1536, 256>>>(x_seq, w_fovea, w_periph);
    k_logits<<<512, 256>>>(head_w, head_b, route_w, route_b, out);
    k_final<<<33, 128>>>(out);
}

// round 17
// speedup vs baseline: 1.1422x; 1.0441x over previous
#include <cuda_runtime.h>
#include <math.h>

#define T_   32
#define B_   32
#define H_   128
#define W_   128

// output layout offsets (floats)
#define OFF_LOGITS 4096
#define OFF_SR     135168
#define OFF_ACTIVE 135170
#define OFF_ROUTE  135171
#define OFF_CHAN   135427

// ---------------- persistent device state ----------------
__device__ float g_scores[T_ * B_ * 256];
__device__ __align__(16) float g_gate[T_ * B_ * 64];   // float2-loaded
__device__ int   g_y0[T_ * B_], g_x0[T_ * B_];
__device__ int   g_fcnt[T_ * B_ * 96];     // spike counts per (t,b,channel)
__device__ int   g_route[256];
__device__ int   g_chan[64];
__device__ int   g_active;
__device__ __align__(16) float g_rz[T_ * B_ * 64 * 128];  // resized periph frames (32 MB)

// packed fp32x2 FMA (Blackwell FFMA2) — bit-exact IEEE fp32 per lane
__device__ __forceinline__ float2 ffma2(float a, float2 w, float2 c) {
#if __CUDA_ARCH__ >= 1000
    union { float2 f; unsigned long long u; } A, W, C, R;
    A.f = make_float2(a, a); W.f = w; C.f = c;
    asm("fma.rn.f32x2 %0, %1, %2, %3;" : "=l"(R.u) : "l"(A.u), "l"(W.u), "l"(C.u));
    return R.f;
#else
    return make_float2(fmaf(a, w.x, c.x), fmaf(a, w.y, c.y));
#endif
}

// 6 taps of one conv row (3 x-positions x 2 input channels), channel-pair packed.
#define CONV_ROW(rp, wrow, acc) do {                       \
    float2 _i0 = ((const float2*)(rp))[0];                 \
    float2 _i1 = ((const float2*)(rp))[1];                 \
    float2 _i2 = ((const float2*)(rp))[2];                 \
    acc = ffma2(_i0.x, (wrow)[0][0], acc);                 \
    acc = ffma2(_i0.y, (wrow)[0][1], acc);                 \
    acc = ffma2(_i1.x, (wrow)[1][0], acc);                 \
    acc = ffma2(_i1.y, (wrow)[1][1], acc);                 \
    acc = ffma2(_i2.x, (wrow)[2][0], acc);                 \
    acc = ffma2(_i2.y, (wrow)[2][1], acc);                 \
} while (0)

__device__ __forceinline__ float evmask(float v) { return (fabsf(v) > 0.5f) ? v : 0.f; }

// ---------------- init ----------------
__global__ void k_init() {
    int i = blockIdx.x * blockDim.x + threadIdx.x;
    int stride = gridDim.x * blockDim.x;
    for (int j = i; j < T_ * B_ * 96; j += stride) g_fcnt[j] = 0;
    if (i < 256) g_route[i] = 0;
    if (i < 64)  g_chan[i]  = 0;
    if (i == 0)  g_active   = 0;
}

// ---------------- k_prep ----------------
// blocks [0,1024): per (t,b) scores/argmax/route/active + fovea conv -> sal -> KWTA gate
// blocks [1024, 1024+8192): periph resize precompute -> g_rz (8 output rows per block)
__global__ void __launch_bounds__(256, 4)
k_prep(const float* __restrict__ x_seq, const float* __restrict__ w_fovea) {
    __shared__ __align__(16) float sb[6984];
    int bx = blockIdx.x, tid = threadIdx.x;

    if (bx < 1024) {
        int b = bx & 31, t = bx >> 5;
        int tb = t * 32 + b;
        const float* x = x_seq + (size_t)tb * 32768;

        float* s_sc  = sb;                                   // 256
        unsigned long long* s_key = (unsigned long long*)(sb + 256);  // 256 ull
        int*   s_acnt = (int*)(sb + 768);                    // 256
        float* s_win  = sb + 1024;                           // 34*68 = 2312
        float* s_asum = sb + 3336;                           // 512
        float* s_sal  = sb + 3848;                           // 64
        float* s_thresh = sb + 3912;
        float* s_thr2   = sb + 3913;
        int*   s_y0p = (int*)(sb + 3914);
        int*   s_x0p = (int*)(sb + 3915);

        // ---- part 1: patch scores (same element order as scalar version) ----
        int py = tid >> 4, px = tid & 15;
        float sum = 0.f; int cnt = 0;
        for (int r = 0; r < 8; r++) {
            const float4* row = (const float4*)(x + ((py * 8 + r) * W_ + px * 8) * 2);
#pragma unroll
            for (int k4 = 0; k4 < 4; k4++) {
                float4 v4 = row[k4];
                float a;
                a = fabsf(v4.x); if (a > 0.5f) { cnt++; sum += a; }
                a = fabsf(v4.y); if (a > 0.5f) { cnt++; sum += a; }
                a = fabsf(v4.z); if (a > 0.5f) { cnt++; sum += a; }
                a = fabsf(v4.w); if (a > 0.5f) { cnt++; sum += a; }
            }
        }
        float sc = sum * (1.f / 128.f);
        s_sc[tid] = sc;
        g_scores[tb * 256 + tid] = sc;
        s_acnt[tid] = cnt;
        unsigned int fb = __float_as_uint(sc);   // sc >= 0 -> order-preserving
        s_key[tid] = (((unsigned long long)fb) << 32) | (unsigned long long)(0xFFFFFFFFu - (unsigned)tid);
        __syncthreads();

        // exact top-4 threshold (JAX top_k tie semantics)
        int cg = 0, ceq = 0;
        for (int j = 0; j < 256; j++) {
            float v = s_sc[j];
            cg  += (v > sc);
            ceq += (v == sc);
        }
        if (cg <= 3 && cg + ceq > 3) *s_thresh = sc;

        for (int off = 128; off > 0; off >>= 1) {
            __syncthreads();
            if (tid < off) {
                s_acnt[tid] += s_acnt[tid + off];
                if (s_key[tid + off] > s_key[tid]) s_key[tid] = s_key[tid + off];
            }
        }
        __syncthreads();

        if (sc >= *s_thresh) atomicAdd(&g_route[tid], 1);
        if (tid == 0) {
            atomicAdd(&g_active, s_acnt[0]);
            unsigned int low = (unsigned int)(s_key[0] & 0xFFFFFFFFull);
            int best = (int)(0xFFFFFFFFu - low);
            int cy = (best >> 4) * 8 + 4;
            int cx = (best & 15) * 8 + 4;
            int y0 = cy - 16; y0 = y0 < 0 ? 0 : (y0 > 96 ? 96 : y0);
            int x0 = cx - 16; x0 = x0 < 0 ? 0 : (x0 > 96 ? 96 : x0);
            *s_y0p = y0; *s_x0p = x0;
            g_y0[tb] = y0; g_x0[tb] = x0;
        }

        // ---- part 2: fovea window load (event-masked, zero-padded) ----
        for (int i = tid; i < 34 * 68; i += 256) s_win[i] = 0.f;
        __syncthreads();
        int y0 = *s_y0p, x0 = *s_x0p;       // x0,y0 even -> float4-aligned
        for (int i = tid; i < 512; i += 256) {
            int rr = i >> 4, c4 = i & 15;
            float4 xv = *(const float4*)&x[(size_t)(y0 + rr) * 256 + x0 * 2 + c4 * 4];
            float* dst = &s_win[(rr + 1) * 68 + c4 * 4 + 2];
            dst[0] = evmask(xv.x); dst[1] = evmask(xv.y);
            dst[2] = evmask(xv.z); dst[3] = evmask(xv.w);
        }
        __syncthreads();

        // ---- part 3: conv -> per-channel |ff| sums -> KWTA gate ----
        int p = tid & 31;           // channel pair
        int g = tid >> 5;           // row group (4 rows each)
        float2 w2[3][3][2];
#pragma unroll
        for (int di = 0; di < 3; di++)
#pragma unroll
            for (int dj = 0; dj < 3; dj++)
#pragma unroll
                for (int ci = 0; ci < 2; ci++)
                    w2[di][dj][ci] = *(const float2*)&w_fovea[((di * 3 + dj) * 2 + ci) * 64 + 2 * p];

        float2 asum = make_float2(0.f, 0.f);
        for (int rq = 0; rq < 4; rq++) {
            int row = g * 4 + rq;
#pragma unroll 4
            for (int j = 0; j < 32; j++) {
                float2 acc = make_float2(0.f, 0.f);
#pragma unroll
                for (int di = 0; di < 3; di++) {
                    const float* rp = &s_win[(row + di) * 68 + j * 2];
                    CONV_ROW(rp, w2[di], acc);
                }
                asum.x += fabsf(acc.x);
                asum.y += fabsf(acc.y);
            }
        }
        s_asum[g * 64 + 2 * p]     = asum.x;
        s_asum[g * 64 + 2 * p + 1] = asum.y;
        __syncthreads();
        if (tid < 64) {
            float s = 0.f;
#pragma unroll
            for (int gg = 0; gg < 8; gg++) s += s_asum[gg * 64 + tid];
            s_sal[tid] = s;
        }
        __syncthreads();
        if (tid < 64) {
            float vv = s_sal[tid];
            int cg2 = 0, ce2 = 0;
            for (int j = 0; j < 64; j++) {
                float u = s_sal[j];
                cg2 += (u > vv);
                ce2 += (u == vv);
            }
            if (cg2 <= 15 && cg2 + ce2 > 15) *s_thr2 = vv;
        }
        __syncthreads();
        if (tid < 64) {
            float gt = (s_sal[tid] >= *s_thr2) ? 1.f : 0.f;
            g_gate[tb * 64 + tid] = gt;
            if (gt > 0.f) atomicAdd(&g_chan[tid], 1);
        }
    } else {
        // ================= periph resize precompute: 8 output rows per block =================
        int rb = bx - 1024;
        int tb = rb >> 3;
        int oy0 = (rb & 7) * 8;
        int hr0 = 2 * oy0 - 1;              // global x-row of local h row 0 (18 rows)
        const float* x = x_seq + (size_t)tb * 32768;

        float* s_x = sb;                    // [18][260] zero-padded cols
        float* s_h = sb + 4680;             // [18][128]

        for (int i = tid; i < 4680; i += 256) s_x[i] = 0.f;
        __syncthreads();
        for (int i = tid; i < 18 * 64; i += 256) {      // 64 float4 per row
            int r = i >> 6, c4 = i & 63;
            int gr = hr0 + r;
            if (gr >= 0 && gr < 128) {
                float4 xv = *(const float4*)&x[(size_t)gr * 256 + c4 * 4];
                float* dst = &s_x[r * 260 + 2 + c4 * 4];
                dst[0] = evmask(xv.x); dst[1] = evmask(xv.y);
                dst[2] = evmask(xv.z); dst[3] = evmask(xv.w);
            }
        }
        __syncthreads();
        // horizontal resize (exact JAX antialias-linear weights; OOB taps weight 0)
        for (int i = tid; i < 2304; i += 256) {
            int r = i >> 7, rest = i & 127;
            int ox = rest >> 1, c = rest & 1;
            int kb; float w0, w1, wm, w3;
            if (ox == 0)       { kb = -1;  w0 = 0.f;       w1 = 3.f / 7.f; wm = 3.f / 7.f; w3 = 1.f / 7.f; }
            else if (ox == 63) { kb = 125; w0 = 1.f / 7.f; w1 = 3.f / 7.f; wm = 3.f / 7.f; w3 = 0.f; }
            else               { kb = 2 * ox - 1; w0 = 0.125f; w1 = 0.375f; wm = 0.375f; w3 = 0.125f; }
            const float* xr = &s_x[r * 260 + 2 + c];
            float vv = w0 * xr[kb * 2] + w1 * xr[(kb + 1) * 2]
                     + wm * xr[(kb + 2) * 2] + w3 * xr[(kb + 3) * 2];
            s_h[i] = vv;
        }
        __syncthreads();
        // vertical resize + store
        for (int i = tid; i < 1024; i += 256) {
            int lr = i >> 7, rest = i & 127;
            int oy = oy0 + lr;
            int jb; float w0, w1, wm, w3;
            if (oy == 0)       { jb = -1;  w0 = 0.f;       w1 = 3.f / 7.f; wm = 3.f / 7.f; w3 = 1.f / 7.f; }
            else if (oy == 63) { jb = 125; w0 = 1.f / 7.f; w1 = 3.f / 7.f; wm = 3.f / 7.f; w3 = 0.f; }
            else               { jb = 2 * oy - 1; w0 = 0.125f; w1 = 0.375f; wm = 0.375f; w3 = 0.125f; }
            int base = jb - hr0;
            float vv = w0 * s_h[base * 128 + rest]       + w1 * s_h[(base + 1) * 128 + rest]
                     + wm * s_h[(base + 2) * 128 + rest] + w3 * s_h[(base + 3) * 128 + rest];
            g_rz[(size_t)tb * 8192 + (size_t)oy * 128 + rest] = vv;
        }
    }
}

// ---------------- k_lif: 8-t staging + packed counters + staged gates ----------------
// blocks [0,512): fovea   — b = bx>>4, 2-row tile = bx&15
// blocks [512,1536): periph — b = (bx-512)>>5, 2-row tile = (bx-512)&31
__global__ void __launch_bounds__(256, 4)
k_lif(const float* __restrict__ x_seq,
      const float* __restrict__ w_fovea,
      const float* __restrict__ w_periph) {
    __shared__ __align__(16) float sbuf[5248];
    __shared__ int s_y[32], s_x[32];
    int bx = blockIdx.x;
    int tid = threadIdx.x;

    if (bx < 512) {
        // ================= fovea: 8-t staged windows + gates, conv + LIF ==========
        int b = bx >> 4, tile = bx & 15;
        float*    s_in   = sbuf;                       // [8 t][4 rows][68] (t stride 272)
        float*    s_gate = sbuf + 2176;                // [8 t][64]
        unsigned* s_pk   = (unsigned*)(sbuf + 2688);   // [32 t][32 pair] packed c0|(c1<<16)

        for (int i = tid; i < 2176; i += 256) s_in[i] = 0.f;
        for (int i = tid; i < 1024; i += 256) s_pk[i] = 0u;
        if (tid < 32) { s_y[tid] = g_y0[tid * 32 + b]; s_x[tid] = g_x0[tid * 32 + b]; }

        int p  = tid & 31;         // channel pair (broadcast LDS within warp)
        int q  = (tid >> 5) & 1;   // row within tile
        int xq = tid >> 6;         // x quarter (0..3): 8 positions each

        float2 w2[3][3][2];
#pragma unroll
        for (int di = 0; di < 3; di++)
#pragma unroll
            for (int dj = 0; dj < 3; dj++)
#pragma unroll
                for (int ci = 0; ci < 2; ci++)
                    w2[di][dj][ci] = *(const float2*)&w_fovea[((di * 3 + dj) * 2 + ci) * 64 + 2 * p];

        float2 v[8];
#pragma unroll
        for (int j = 0; j < 8; j++) v[j] = make_float2(0.f, 0.f);

        int r0 = tile * 2;

        for (int ph = 0; ph < 4; ph++) {
            __syncthreads();   // prev phase conv done (covers init on ph=0)
            // stage 8 timesteps of gaze windows
            for (int i = tid; i < 512; i += 256) {
                int tt = i >> 6, rr = (i >> 4) & 3, c4 = i & 15;
                int t = ph * 8 + tt;
                int lrow = r0 - 1 + rr;
                if (lrow >= 0 && lrow < 32) {
                    const float* x = x_seq + (size_t)(t * 32 + b) * 32768;
                    float4 xv = *(const float4*)&x[(size_t)(s_y[t] + lrow) * 256 + s_x[t] * 2 + c4 * 4];
                    float* dst = &s_in[tt * 272 + rr * 68 + c4 * 4 + 2];
                    dst[0] = evmask(xv.x); dst[1] = evmask(xv.y);
                    dst[2] = evmask(xv.z); dst[3] = evmask(xv.w);
                }
            }
            // stage 8 timesteps of gates (coalesced)
            for (int i = tid; i < 512; i += 256) {
                int tt = i >> 6, c = i & 63;
                s_gate[i] = g_gate[((ph * 8 + tt) * 32 + b) * 64 + c];
            }
            __syncthreads();

#pragma unroll
            for (int tt = 0; tt < 8; tt++) {
                int t = ph * 8 + tt;
                float2 g2 = *(const float2*)&s_gate[tt * 64 + 2 * p];
                const float* tbase = &s_in[tt * 272];
                int c0 = 0, c1 = 0;
#pragma unroll
                for (int j = 0; j < 8; j++) {
                    int xx = xq * 8 + j;
                    float2 acc = make_float2(0.f, 0.f);
#pragma unroll
                    for (int di = 0; di < 3; di++) {
                        const float* rp = &tbase[(q + di) * 68 + xx * 2];
                        CONV_ROW(rp, w2[di], acc);
                    }
                    float vx = 0.9f * v[j].x + acc.x * g2.x;
                    float vy = 0.9f * v[j].y + acc.y * g2.y;
                    if (vx > 1.0f) { vx -= 1.0f; c0++; }
                    if (vy > 1.0f) { vy -= 1.0f; c1++; }
                    v[j].x = vx; v[j].y = vy;
                }
                atomicAdd(&s_pk[t * 32 + p], (unsigned)(c0 | (c1 << 16)));
            }
        }
        __syncthreads();
        for (int i = tid; i < 1024; i += 256) {
            int t = i >> 5, pp = i & 31;
            unsigned val = s_pk[i];
            if (val) {
                int a = (int)(val & 0xFFFFu), bb = (int)(val >> 16);
                int base = (t * 32 + b) * 96 + 2 * pp;
                if (a)  atomicAdd(&g_fcnt[base],     a);
                if (bb) atomicAdd(&g_fcnt[base + 1], bb);
            }
        }
    } else {
        // ================= periph: 8-t staged windows, conv + LIF ==========
        int pbx = bx - 512;
        int b = pbx >> 5, tile = pbx & 31;        // output rows [2*tile, 2*tile+2)
        float*    s_rz = sbuf;                     // [8 t][4 rows][132] (t stride 528)
        unsigned* s_pk = (unsigned*)(sbuf + 4224); // [32 t][16 pair] packed

        for (int i = tid; i < 4224; i += 256) s_rz[i] = 0.f;
        for (int i = tid; i < 512;  i += 256) s_pk[i] = 0u;

        int p  = tid & 15;   // channel pair
        int xg = tid >> 4;   // x group (0..15): 4 positions each

        float2 w2[3][3][2];
#pragma unroll
        for (int di = 0; di < 3; di++)
#pragma unroll
            for (int dj = 0; dj < 3; dj++)
#pragma unroll
                for (int ci = 0; ci < 2; ci++)
                    w2[di][dj][ci] = *(const float2*)&w_periph[((di * 3 + dj) * 2 + ci) * 32 + 2 * p];

        float2 v[2][4];
#pragma unroll
        for (int yo = 0; yo < 2; yo++)
#pragma unroll
            for (int j = 0; j < 4; j++) v[yo][j] = make_float2(0.f, 0.f);

        for (int ph = 0; ph < 4; ph++) {
            __syncthreads();   // prev phase conv done (covers zero-init on ph=0)
            // stage 8 timesteps of window rows 2*tile-1..2*tile+2 (OOB rows stay zero)
            for (int i = tid; i < 1024; i += 256) {
                int tt = i >> 7, lr = (i >> 5) & 3, c4 = i & 31;
                int row = 2 * tile - 1 + lr;
                if (row >= 0 && row < 64) {
                    int t = ph * 8 + tt;
                    float4 rv = *(const float4*)&g_rz[(size_t)(t * 32 + b) * 8192 + (size_t)row * 128 + c4 * 4];
                    float* dst = &s_rz[tt * 528 + lr * 132 + c4 * 4 + 2];
                    dst[0] = rv.x; dst[1] = rv.y; dst[2] = rv.z; dst[3] = rv.w;
                }
            }
            __syncthreads();

#pragma unroll
            for (int tt = 0; tt < 8; tt++) {
                int t = ph * 8 + tt;
                const float* tbase = &s_rz[tt * 528];
                int c0 = 0, c1 = 0;
#pragma unroll
                for (int yo = 0; yo < 2; yo++) {
#pragma unroll
                    for (int j = 0; j < 4; j++) {
                        int xx = 4 * xg + j;
                        float2 acc = make_float2(0.f, 0.f);
#pragma unroll
                        for (int di = 0; di < 3; di++) {
                            const float* rp = &tbase[(yo + di) * 132 + xx * 2];
                            CONV_ROW(rp, w2[di], acc);
                        }
                        float vx = 0.9f * v[yo][j].x + acc.x;
                        float vy = 0.9f * v[yo][j].y + acc.y;
                        if (vx > 1.0f) { vx -= 1.0f; c0++; }
                        if (vy > 1.0f) { vy -= 1.0f; c1++; }
                        v[yo][j].x = vx; v[yo][j].y = vy;
                    }
                }
                atomicAdd(&s_pk[t * 16 + p], (unsigned)(c0 | (c1 << 16)));
            }
        }
        __syncthreads();
        for (int i = tid; i < 512; i += 256) {
            int t = i >> 4, pp = i & 15;
            unsigned val = s_pk[i];
            if (val) {
                int a = (int)(val & 0xFFFFu), bb = (int)(val >> 16);
                int base = (t * 32 + b) * 96 + 64 + 2 * pp;
                if (a)  atomicAdd(&g_fcnt[base],     a);
                if (bb) atomicAdd(&g_fcnt[base + 1], bb);
            }
        }
    }
}

// ---------------- k_logits: 2 tb per block, 512 blocks, coalesced weights ----------------
__global__ void __launch_bounds__(256, 6)
k_logits(const float* __restrict__ head_w, const float* __restrict__ head_b,
         const float* __restrict__ route_w, const float* __restrict__ route_b,
         float* __restrict__ out) {
    int g = blockIdx.x;      // tb = g*2 + ib
    int tid = threadIdx.x;
    int ib = tid >> 7, o = tid & 127;
    __shared__ float s_f[2][96];
    __shared__ float s_s[2][256];
    for (int i = tid; i < 2 * 96; i += 256) {
        int jb = i / 96, c = i % 96;
        float scale = (c < 64) ? (1.f / 1024.f) : (1.f / 4096.f);
        s_f[jb][c] = (float)g_fcnt[(g * 2 + jb) * 96 + c] * scale;
    }
    for (int i = tid; i < 2 * 256; i += 256) {
        int jb = i >> 8, k = i & 255;
        s_s[jb][k] = g_scores[(g * 2 + jb) * 256 + k];
    }
    __syncthreads();
    float acc = head_b[o] + route_b[o];
    for (int c = 0; c < 96; c++)  acc = fmaf(s_f[ib][c], head_w[c * 128 + o], acc);
    for (int k = 0; k < 256; k++) acc = fmaf(s_s[ib][k], route_w[k * 128 + o], acc);
    out[OFF_LOGITS + (size_t)(g * 2 + ib) * 128 + o] = acc;
}

// ---------------- k_final: mean over T + stats ----------------
__global__ void k_final(float* __restrict__ out) {
    int bid = blockIdx.x, tid = threadIdx.x;
    if (bid < 32) {
        float acc = 0.f;
        for (int t = 0; t < 32; t++)
            acc += out[OFF_LOGITS + (size_t)(t * 32 + bid) * 128 + tid];
        out[bid * 128 + tid] = acc * (1.f / 32.f);
    } else {
        for (int k = tid; k < 256; k += 128)
            out[OFF_ROUTE + k] = (float)g_route[k] * (1.f / 1024.f);
        if (tid < 64)
            out[OFF_CHAN + tid] = (float)g_chan[tid] * (1.f / 1024.f);
        __shared__ int r0[128], r1[128];
        int c0 = 0, c1 = 0;
        for (int i = tid; i < T_ * B_ * 96; i += 128) {
            int c = i % 96;
            int vv = g_fcnt[i];
            if (c < 64) c0 += vv; else c1 += vv;
        }
        r0[tid] = c0; r1[tid] = c1;
        __syncthreads();
        for (int off = 64; off > 0; off >>= 1) {
            if (tid < off) { r0[tid] += r0[tid + off]; r1[tid] += r1[tid + off]; }
            __syncthreads();
        }
        if (tid == 0) {
            out[OFF_SR + 0] = (float)r0[0] * (1.f / 67108864.f);    // T*B*32*32*64
            out[OFF_SR + 1] = (float)r1[0] * (1.f / 134217728.f);   // T*B*64*64*32
            out[OFF_ACTIVE] = (float)g_active * (1.f / 33554432.f); // T*B*128*128*2
        }
    }
}

// ---------------- launch ----------------
extern "C" void kernel_launch(void* const* d_in, const int* in_sizes, int n_in,
                              void* d_out, int out_size) {
    const float* x_seq    = (const float*)d_in[0];
    const float* w_fovea  = (const float*)d_in[1];
    const float* w_periph = (const float*)d_in[2];
    const float* head_w   = (const float*)d_in[3];
    const float* head_b   = (const float*)d_in[4];
    const float* route_w  = (const float*)d_in[5];
    const float* route_b  = (const float*)d_in[6];
    float* out = (float*)d_out;

    k_init<<<384, 256>>>();
    k_prep<<<1024 + 8192, 256>>>(x_seq, w_fovea);
    k_lif<<<1536, 256>>>(x_seq, w_fovea, w_periph);
    k_logits<<<512, 256>>>(head_w, head_b, route_w, route_b, out);
    k_final<<<33, 128>>>(out);
}